// round 4
// baseline (speedup 1.0000x reference)
#include <cuda_runtime.h>
#include <cstdint>

// ---------------- problem constants ----------------
#define BATCH   16384
#define DIN     1408
#define DHID    256
#define DOUT    3
#define NHEADS  32

// ---------------- tiling ----------------
#define MT      128          // CTA rows
#define KT      32           // K per stage
#define NK      (DIN / KT)   // 44
#define NSTG    3
#define NTH     256          // 8 warps: 2 (M) x 4 (N), warp tile 64x64

// ---------------- smem layout ----------------
// rows padded to 40 floats (160B): conflict-free for v2 fragment loads
#define RPAD    40
#define A_SZ    (MT * RPAD * 4)             // 20480
#define B_SZ    (DHID * RPAD * 4)           // 40960
#define STG_SZ  (A_SZ + B_SZ)               // 61440
#define SM_EP   (NSTG * STG_SZ)             // 184320 : 256 x float4 table
#define SM_RED  0                           // reuse stage 0 region post-loop
#define SMEM_TOTAL (SM_EP + DHID * 16)      // 188416

// ---------------- scratch (alloc-free rule: device globals) ----------------
// Both hold tf32-rounded data with K permuted within each 8-block:
//   kperm = (k & ~7) | (2*(k&3) + ((k&7)>>2))
__device__ __align__(16) float g_Ap[(size_t)BATCH * DIN];             // [m][kperm]
__device__ __align__(16) float g_W1T[(size_t)NHEADS * DHID * DIN];    // [h][n][kperm]

// ---------------- helpers ----------------
__device__ __forceinline__ uint32_t smem_u32(const void* p) {
    uint32_t a;
    asm("{ .reg .u64 t; cvta.to.shared.u64 t, %1; cvt.u32.u64 %0, t; }" : "=r"(a) : "l"(p));
    return a;
}

__device__ __forceinline__ void cp_async16(uint32_t dst, const void* src) {
    asm volatile("cp.async.cg.shared.global [%0], [%1], 16;\n" :: "r"(dst), "l"(src));
}

__device__ __forceinline__ float2 lds_f2(uint32_t addr) {
    float2 v;
    asm volatile("ld.shared.v2.f32 {%0,%1}, [%2];" : "=f"(v.x), "=f"(v.y) : "r"(addr));
    return v;
}

__device__ __forceinline__ void mma_tf32(float* d, uint32_t a0, uint32_t a1, uint32_t a2,
                                         uint32_t a3, uint32_t b0, uint32_t b1) {
    asm volatile(
        "mma.sync.aligned.m16n8k8.row.col.f32.tf32.tf32.f32 "
        "{%0,%1,%2,%3}, {%4,%5,%6,%7}, {%8,%9}, {%0,%1,%2,%3};"
        : "+f"(d[0]), "+f"(d[1]), "+f"(d[2]), "+f"(d[3])
        : "r"(a0), "r"(a1), "r"(a2), "r"(a3), "r"(b0), "r"(b1));
}

__device__ __forceinline__ uint32_t rna_tf32(float v) {
    uint32_t r;
    asm("cvt.rna.tf32.f32 %0, %1;" : "=r"(r) : "f"(v));
    return r;
}

// ---------------- prep 1: A -> tf32, k-permuted ----------------
// Each thread handles 8 consecutive floats (one permutation block).
__global__ void k_prep_a(const float* __restrict__ A) {
    int i = blockIdx.x * blockDim.x + threadIdx.x;       // block index
    if (i >= (BATCH * DIN) / 8) return;
    const float4* src = reinterpret_cast<const float4*>(A) + 2 * i;
    float4 v0 = src[0], v1 = src[1];                      // k 0-3, k 4-7
    uint4 o0, o1;                                         // interleaved
    o0.x = rna_tf32(v0.x); o0.y = rna_tf32(v1.x);
    o0.z = rna_tf32(v0.y); o0.w = rna_tf32(v1.y);
    o1.x = rna_tf32(v0.z); o1.y = rna_tf32(v1.z);
    o1.z = rna_tf32(v0.w); o1.w = rna_tf32(v1.w);
    uint4* dst = reinterpret_cast<uint4*>(g_Ap) + 2 * i;
    dst[0] = o0; dst[1] = o1;
}

// ---------------- prep 2: W1 [h][f][o] -> [h][n][fperm], tf32 ----------------
__global__ void k_prep_w(const float* __restrict__ W1) {
    __shared__ float tile[32][33];
    int h = blockIdx.z;
    int f0 = blockIdx.x * 32, o0 = blockIdx.y * 32;
    int tx = threadIdx.x, ty = threadIdx.y;
    const float* src = W1 + (size_t)h * DIN * DHID;
#pragma unroll
    for (int i = 0; i < 32; i += 8)
        tile[ty + i][tx] = src[(size_t)(f0 + ty + i) * DHID + (o0 + tx)];
    __syncthreads();
    float* dst = g_W1T + (size_t)h * DHID * DIN;
#pragma unroll
    for (int i = 0; i < 32; i += 8) {
        int f = f0 + tx;
        int fp = (f & ~7) | (2 * (f & 3) + ((f & 7) >> 2));
        dst[(size_t)(o0 + ty + i) * DIN + fp] =
            __uint_as_float(rna_tf32(tile[tx][ty + i]));
    }
}

// ---------------- stage loader ----------------
__device__ __forceinline__ void load_stage(uint32_t stage_base, const float* __restrict__ Ag,
                                           const float* __restrict__ Bg, int kt, int tid) {
    const float* ak = Ag + kt * KT;
#pragma unroll
    for (int i = 0; i < 4; i++) {               // A: 128 rows x 8 granules
        int gi = tid + i * NTH;
        int r = gi >> 3, c = gi & 7;
        cp_async16(stage_base + r * (RPAD * 4) + c * 16, ak + (size_t)r * DIN + c * 4);
    }
    const float* bk = Bg + kt * KT;
#pragma unroll
    for (int i = 0; i < 8; i++) {               // B: 256 rows x 8 granules
        int gi = tid + i * NTH;
        int r = gi >> 3, c = gi & 7;
        cp_async16(stage_base + A_SZ + r * (RPAD * 4) + c * 16, bk + (size_t)r * DIN + c * 4);
    }
}

// ---------------- main fused kernel ----------------
__global__ void __launch_bounds__(NTH, 1) mano_gemm(
    const float* __restrict__ b1, const float* __restrict__ W2,
    const float* __restrict__ b2, float* __restrict__ out) {
    extern __shared__ char smem[];
    const uint32_t sb = smem_u32(smem);
    const int tid = threadIdx.x;
    const int wid = tid >> 5, lane = tid & 31;
    const int g = lane >> 2, tig = lane & 3;
    const int wm = wid & 1, wn = wid >> 1;       // warp tile: rows wm*64, cols wn*64
    const int head = blockIdx.x;                 // head-fastest: L2 reuse
    const int m0 = blockIdx.y * MT;

    const float* Ag = g_Ap + (size_t)m0 * DIN;
    const float* Bg = g_W1T + (size_t)head * DHID * DIN;

    // epilogue table: {b1[c], W2[c][0..2]}
    if (tid < DHID) {
        const float* b1h = b1 + head * DHID;
        const float* w2h = W2 + (size_t)head * DHID * DOUT;
        float4 v;
        v.x = b1h[tid];
        v.y = w2h[tid * 3 + 0];
        v.z = w2h[tid * 3 + 1];
        v.w = w2h[tid * 3 + 2];
        *reinterpret_cast<float4*>(smem + SM_EP + tid * 16) = v;
    }

    load_stage(sb + 0 * STG_SZ, Ag, Bg, 0, tid);
    asm volatile("cp.async.commit_group;\n");
    load_stage(sb + 1 * STG_SZ, Ag, Bg, 1, tid);
    asm volatile("cp.async.commit_group;\n");

    float acc[4][8][4];
#pragma unroll
    for (int t = 0; t < 4; t++)
#pragma unroll
        for (int j = 0; j < 8; j++)
#pragma unroll
            for (int e = 0; e < 4; e++) acc[t][j][e] = 0.f;

    for (int kt = 0; kt < NK; kt++) {
        const int buf = kt % NSTG;
        asm volatile("cp.async.wait_group 1;\n");   // stage kt landed
        __syncthreads();                            // all warps done with prior buffer

        if (kt + 2 < NK)
            load_stage(sb + ((kt + 2) % NSTG) * STG_SZ, Ag, Bg, kt + 2, tid);
        asm volatile("cp.async.commit_group;\n");

        const uint32_t a_base = sb + buf * STG_SZ;
        const uint32_t b_base = a_base + A_SZ;
#pragma unroll
        for (int k8 = 0; k8 < 4; k8++) {
            const uint32_t koff = (k8 * 8 + 2 * tig) * 4;
            // A fragments: v2 gives (k=tig, k=tig+4) adjacent after permutation
            uint32_t a0[4], a1[4], a2[4], a3[4];
#pragma unroll
            for (int t = 0; t < 4; t++) {
                int r0 = wm * 64 + t * 16 + g;
                float2 lo = lds_f2(a_base + r0 * (RPAD * 4) + koff);
                float2 hi = lds_f2(a_base + (r0 + 8) * (RPAD * 4) + koff);
                a0[t] = __float_as_uint(lo.x);
                a1[t] = __float_as_uint(hi.x);
                a2[t] = __float_as_uint(lo.y);
                a3[t] = __float_as_uint(hi.y);
            }
#pragma unroll
            for (int j = 0; j < 8; j++) {
                int n = wn * 64 + j * 8 + g;
                float2 bv = lds_f2(b_base + n * (RPAD * 4) + koff);
                uint32_t b0 = __float_as_uint(bv.x);
                uint32_t b1r = __float_as_uint(bv.y);
#pragma unroll
                for (int t = 0; t < 4; t++)
                    mma_tf32(acc[t][j], a0[t], a1[t], a2[t], a3[t], b0, b1r);
            }
        }
    }

    __syncthreads();    // done with stage smem; reuse region 0 for reduction

    // ---- fused epilogue: h = relu(acc + b1); partial[p] += h * W2[:,p] ----
    float s[4][2][3];
#pragma unroll
    for (int t = 0; t < 4; t++)
#pragma unroll
        for (int h = 0; h < 2; h++)
            s[t][h][0] = s[t][h][1] = s[t][h][2] = 0.f;

#pragma unroll
    for (int j = 0; j < 8; j++) {
#pragma unroll
        for (int e = 0; e < 2; e++) {
            const int c = wn * 64 + j * 8 + tig * 2 + e;
            const float4 wv = *reinterpret_cast<const float4*>(smem + SM_EP + c * 16);
#pragma unroll
            for (int t = 0; t < 4; t++) {
#pragma unroll
                for (int h = 0; h < 2; h++) {
                    float hv = fmaxf(acc[t][j][h * 2 + e] + wv.x, 0.f);
                    s[t][h][0] = fmaf(hv, wv.y, s[t][h][0]);
                    s[t][h][1] = fmaf(hv, wv.z, s[t][h][1]);
                    s[t][h][2] = fmaf(hv, wv.w, s[t][h][2]);
                }
            }
        }
    }

#pragma unroll
    for (int t = 0; t < 4; t++)
#pragma unroll
        for (int h = 0; h < 2; h++)
#pragma unroll
            for (int p = 0; p < 3; p++) {
                float v = s[t][h][p];
                v += __shfl_xor_sync(0xffffffffu, v, 1);
                v += __shfl_xor_sync(0xffffffffu, v, 2);
                s[t][h][p] = v;
            }

    float* red = reinterpret_cast<float*>(smem + SM_RED);
    if (tig == 0) {
#pragma unroll
        for (int t = 0; t < 4; t++)
#pragma unroll
            for (int h = 0; h < 2; h++) {
                int row = wm * 64 + t * 16 + h * 8 + g;
#pragma unroll
                for (int p = 0; p < 3; p++)
                    red[(wn * MT + row) * 3 + p] = s[t][h][p];
            }
    }
    __syncthreads();

    for (int i = tid; i < MT * 3; i += NTH) {
        int r = i / 3, p = i % 3;
        float v = red[(0 * MT + r) * 3 + p] + red[(1 * MT + r) * 3 + p]
                + red[(2 * MT + r) * 3 + p] + red[(3 * MT + r) * 3 + p]
                + __ldg(b2 + head * DOUT + p);
        out[(size_t)(m0 + r) * (NHEADS * DOUT) + head * DOUT + p] = v;
    }
}

// ---------------- launch ----------------
extern "C" void kernel_launch(void* const* d_in, const int* in_sizes, int n_in,
                              void* d_out, int out_size) {
    const float* total_feat = (const float*)d_in[0];
    const float* W1 = (const float*)d_in[1];
    const float* b1 = (const float*)d_in[2];
    const float* W2 = (const float*)d_in[3];
    const float* b2 = (const float*)d_in[4];
    float* out = (float*)d_out;

    int nblk = (BATCH * DIN) / 8;
    k_prep_a<<<(nblk + 255) / 256, 256>>>(total_feat);
    k_prep_w<<<dim3(DIN / 32, DHID / 32, NHEADS), dim3(32, 8)>>>(W1);

    cudaFuncSetAttribute(mano_gemm, cudaFuncAttributeMaxDynamicSharedMemorySize, SMEM_TOTAL);
    mano_gemm<<<dim3(NHEADS, BATCH / MT), NTH, SMEM_TOTAL>>>(b1, W2, b2, out);
}

// round 7
// speedup vs baseline: 1.1292x; 1.1292x over previous
#include <cuda_runtime.h>
#include <cstdint>

// ---------------- problem constants ----------------
#define BATCH   16384
#define DIN     1408
#define DHID    256
#define DOUT    3
#define NHEADS  32

// ---------------- tiling ----------------
#define MT      128          // CTA rows
#define KT      32           // K per stage
#define NK      (DIN / KT)   // 44
#define NSTG    3
#define NTH     256          // 8 warps: 2 (M) x 4 (N), warp tile 64x64

// ---------------- smem layout (bytes, dynamic) ----------------
#define A_PAD   36           // floats per A row (conflict-free: bank = 4g+tig)
#define A_SZ    (MT * A_PAD * 4)            // 18432
// B: 32 rows x 256 floats, row stride 1024B, 16B-granule XOR swizzle (c ^ (k&3))
#define B_SZ    (KT * DHID * 4)             // 32768
#define STG_SZ  (A_SZ + B_SZ)               // 51200
#define SM_EP   (NSTG * STG_SZ)             // 153600 : 256 x float4 table
#define SM_RED  0                           // reuse stage 0 region post-loop
#define SMEM_TOTAL (SM_EP + DHID * 16)      // 157696

// ---------------- scratch (alloc-free rule: device globals) ----------------
__device__ __align__(16) float g_Arnd[(size_t)BATCH * DIN];           // A rounded to tf32
__device__ __align__(16) float g_W1r[(size_t)NHEADS * DIN * DHID];    // W1 rounded to tf32

#define NA4 ((BATCH * DIN) / 4)
#define NW4 ((NHEADS * DIN * DHID) / 4)

// ---------------- helpers ----------------
__device__ __forceinline__ uint32_t smem_u32(const void* p) {
    uint32_t a;
    asm("{ .reg .u64 t; cvta.to.shared.u64 t, %1; cvt.u32.u64 %0, t; }" : "=r"(a) : "l"(p));
    return a;
}

__device__ __forceinline__ void cp_async16(uint32_t dst, const void* src) {
    asm volatile("cp.async.cg.shared.global [%0], [%1], 16;\n" :: "r"(dst), "l"(src));
}

__device__ __forceinline__ float lds_f(uint32_t addr) {
    float v;
    asm volatile("ld.shared.f32 %0, [%1];" : "=f"(v) : "r"(addr));
    return v;
}

__device__ __forceinline__ void mma_tf32(float* d, const uint32_t* a, uint32_t b0, uint32_t b1) {
    asm volatile(
        "mma.sync.aligned.m16n8k8.row.col.f32.tf32.tf32.f32 "
        "{%0,%1,%2,%3}, {%4,%5,%6,%7}, {%8,%9}, {%0,%1,%2,%3};"
        : "+f"(d[0]), "+f"(d[1]), "+f"(d[2]), "+f"(d[3])
        : "r"(a[0]), "r"(a[1]), "r"(a[2]), "r"(a[3]), "r"(b0), "r"(b1));
}

// ---------------- prep: RN-round fp32 -> tf32 (A and W1 in one launch) ----------------
__global__ void k_prep(const float* __restrict__ A, const float* __restrict__ W) {
    int i = blockIdx.x * blockDim.x + threadIdx.x;
    if (i >= NA4 + NW4) return;
    const float4* src;
    uint4* dst;
    if (i < NA4) {
        src = reinterpret_cast<const float4*>(A) + i;
        dst = reinterpret_cast<uint4*>(g_Arnd) + i;
    } else {
        src = reinterpret_cast<const float4*>(W) + (i - NA4);
        dst = reinterpret_cast<uint4*>(g_W1r) + (i - NA4);
    }
    float4 v = *src;
    uint4 o;
    asm("cvt.rna.tf32.f32 %0, %1;" : "=r"(o.x) : "f"(v.x));
    asm("cvt.rna.tf32.f32 %0, %1;" : "=r"(o.y) : "f"(v.y));
    asm("cvt.rna.tf32.f32 %0, %1;" : "=r"(o.z) : "f"(v.z));
    asm("cvt.rna.tf32.f32 %0, %1;" : "=r"(o.w) : "f"(v.w));
    *dst = o;
}

// ---------------- stage loader ----------------
__device__ __forceinline__ void load_stage(uint32_t stage_base, const float* __restrict__ Ag,
                                           const float* __restrict__ Bg, int kt, int tid) {
    const float* ak = Ag + kt * KT;
#pragma unroll
    for (int i = 0; i < 4; i++) {               // A: 128 rows x 8 granules of 16B
        int gi = tid + i * NTH;
        int r = gi >> 3, c = gi & 7;
        cp_async16(stage_base + r * (A_PAD * 4) + c * 16, ak + (size_t)r * DIN + c * 4);
    }
    const float* bk = Bg + (size_t)kt * KT * DHID;
#pragma unroll
    for (int i = 0; i < 8; i++) {               // B: 32 rows x 64 granules, XOR swizzled
        int gi = tid + i * NTH;
        int r = gi >> 6, c = gi & 63;
        cp_async16(stage_base + A_SZ + r * 1024 + 16 * (c ^ (r & 3)),
                   bk + r * DHID + c * 4);
    }
}

// ---------------- main fused kernel ----------------
__global__ void __launch_bounds__(NTH, 1) mano_gemm(
    const float* __restrict__ b1, const float* __restrict__ W2,
    const float* __restrict__ b2, float* __restrict__ out) {
    extern __shared__ char smem[];
    const uint32_t sb = smem_u32(smem);
    const int tid = threadIdx.x;
    const int wid = tid >> 5, lane = tid & 31;
    const int g = lane >> 2, tig = lane & 3;     // groupID / threadID-in-group
    const int wm = wid & 1, wn = wid >> 1;       // warp tile: rows wm*64, cols wn*64
    const int head = blockIdx.x;                 // head-fastest: L2 reuse of A slab + all W1
    const int m0 = blockIdx.y * MT;

    const float* Ag = g_Arnd + (size_t)m0 * DIN;
    const float* Bg = g_W1r + (size_t)head * DIN * DHID;

    // epilogue table: wb[c] = {b1[c], W2[c][0], W2[c][1], W2[c][2]}
    if (tid < DHID) {
        const float* b1h = b1 + head * DHID;
        const float* w2h = W2 + (size_t)head * DHID * DOUT;
        float4 v;
        v.x = b1h[tid];
        v.y = w2h[tid * 3 + 0];
        v.z = w2h[tid * 3 + 1];
        v.w = w2h[tid * 3 + 2];
        *reinterpret_cast<float4*>(smem + SM_EP + tid * 16) = v;
    }

    // prologue: stages 0,1 in flight
    load_stage(sb + 0 * STG_SZ, Ag, Bg, 0, tid);
    asm volatile("cp.async.commit_group;\n");
    load_stage(sb + 1 * STG_SZ, Ag, Bg, 1, tid);
    asm volatile("cp.async.commit_group;\n");

    // precomputed swizzled B column byte-offsets (within a row) per j
    uint32_t nsw[8];
#pragma unroll
    for (int j = 0; j < 8; j++) {
        int n = wn * 64 + j * 8 + g;
        nsw[j] = 16u * ((uint32_t)(n >> 2) ^ (uint32_t)tig) + 4u * (n & 3);
    }

    float acc[4][8][4];
#pragma unroll
    for (int t = 0; t < 4; t++)
#pragma unroll
        for (int j = 0; j < 8; j++)
#pragma unroll
            for (int e = 0; e < 4; e++) acc[t][j][e] = 0.f;

    for (int kt = 0; kt < NK; kt++) {
        const int buf = kt % NSTG;
        asm volatile("cp.async.wait_group 1;\n");   // stage kt landed
        __syncthreads();                            // all warps done with prior buffer

        if (kt + 2 < NK)
            load_stage(sb + ((kt + 2) % NSTG) * STG_SZ, Ag, Bg, kt + 2, tid);
        asm volatile("cp.async.commit_group;\n");

        const uint32_t a_base = sb + buf * STG_SZ;
        const uint32_t b_base = a_base + A_SZ;
#pragma unroll
        for (int k8 = 0; k8 < 4; k8++) {
            const int kk = k8 * 8;
            uint32_t a[4][4];
#pragma unroll
            for (int t = 0; t < 4; t++) {
                int r0 = wm * 64 + t * 16 + g;
                a[t][0] = __float_as_uint(lds_f(a_base + (r0 * A_PAD + kk + tig) * 4));
                a[t][1] = __float_as_uint(lds_f(a_base + ((r0 + 8) * A_PAD + kk + tig) * 4));
                a[t][2] = __float_as_uint(lds_f(a_base + (r0 * A_PAD + kk + 4 + tig) * 4));
                a[t][3] = __float_as_uint(lds_f(a_base + ((r0 + 8) * A_PAD + kk + 4 + tig) * 4));
            }
            // B rows kk+tig and kk+4+tig; (row & 3) == tig for both -> swizzle uses tig
            const uint32_t brow0 = b_base + (uint32_t)(kk + tig) * 1024u;
#pragma unroll
            for (int j = 0; j < 8; j++) {
                uint32_t b0 = __float_as_uint(lds_f(brow0 + nsw[j]));
                uint32_t b1r = __float_as_uint(lds_f(brow0 + 4096u + nsw[j]));
#pragma unroll
                for (int t = 0; t < 4; t++)
                    mma_tf32(acc[t][j], a[t], b0, b1r);
            }
        }
    }

    __syncthreads();    // done reading stage smem; safe to reuse region 0 for reduction

    // ---- fused epilogue: h = relu(acc + b1); partial[p] += h * W2[:,p] ----
    float s[4][2][3];
#pragma unroll
    for (int t = 0; t < 4; t++)
#pragma unroll
        for (int h = 0; h < 2; h++)
            s[t][h][0] = s[t][h][1] = s[t][h][2] = 0.f;

#pragma unroll
    for (int j = 0; j < 8; j++) {
#pragma unroll
        for (int e = 0; e < 2; e++) {
            const int c = wn * 64 + j * 8 + tig * 2 + e;
            const float4 wv = *reinterpret_cast<const float4*>(smem + SM_EP + c * 16);
#pragma unroll
            for (int t = 0; t < 4; t++) {
#pragma unroll
                for (int h = 0; h < 2; h++) {
                    float hv = fmaxf(acc[t][j][h * 2 + e] + wv.x, 0.f);
                    s[t][h][0] = fmaf(hv, wv.y, s[t][h][0]);
                    s[t][h][1] = fmaf(hv, wv.z, s[t][h][1]);
                    s[t][h][2] = fmaf(hv, wv.w, s[t][h][2]);
                }
            }
        }
    }

    // reduce over tig (lanes sharing a row): lane bits 0,1
#pragma unroll
    for (int t = 0; t < 4; t++)
#pragma unroll
        for (int h = 0; h < 2; h++)
#pragma unroll
            for (int p = 0; p < 3; p++) {
                float v = s[t][h][p];
                v += __shfl_xor_sync(0xffffffffu, v, 1);
                v += __shfl_xor_sync(0xffffffffu, v, 2);
                s[t][h][p] = v;
            }

    // cross-warp (wn) reduction through smem: red[wn][row][p]
    float* red = reinterpret_cast<float*>(smem + SM_RED);
    if (tig == 0) {
#pragma unroll
        for (int t = 0; t < 4; t++)
#pragma unroll
            for (int h = 0; h < 2; h++) {
                int row = wm * 64 + t * 16 + h * 8 + g;
#pragma unroll
                for (int p = 0; p < 3; p++)
                    red[(wn * MT + row) * 3 + p] = s[t][h][p];
            }
    }
    __syncthreads();

    for (int i = tid; i < MT * 3; i += NTH) {
        int r = i / 3, p = i % 3;
        float v = red[(0 * MT + r) * 3 + p] + red[(1 * MT + r) * 3 + p]
                + red[(2 * MT + r) * 3 + p] + red[(3 * MT + r) * 3 + p]
                + __ldg(b2 + head * DOUT + p);
        out[(size_t)(m0 + r) * (NHEADS * DOUT) + head * DOUT + p] = v;
    }
}

// ---------------- launch ----------------
extern "C" void kernel_launch(void* const* d_in, const int* in_sizes, int n_in,
                              void* d_out, int out_size) {
    const float* total_feat = (const float*)d_in[0];
    const float* W1 = (const float*)d_in[1];
    const float* b1 = (const float*)d_in[2];
    const float* W2 = (const float*)d_in[3];
    const float* b2 = (const float*)d_in[4];
    float* out = (float*)d_out;

    int total = NA4 + NW4;
    k_prep<<<(total + 255) / 256, 256>>>(total_feat, W1);

    cudaFuncSetAttribute(mano_gemm, cudaFuncAttributeMaxDynamicSharedMemorySize, SMEM_TOTAL);
    mano_gemm<<<dim3(NHEADS, BATCH / MT), NTH, SMEM_TOTAL>>>(b1, W2, b2, out);
}

// round 12
// speedup vs baseline: 1.1518x; 1.0200x over previous
#include <cuda_runtime.h>
#include <cstdint>

// ---------------- problem constants ----------------
#define BATCH   16384
#define DIN     1408
#define DHID    256
#define DOUT    3
#define NHEADS  32

// ---------------- tiling ----------------
#define MT      128          // CTA rows
#define KT      32           // K per stage
#define NK      (DIN / KT)   // 44
#define NSTG    3
#define NTH     256          // 8 warps: 2 (M) x 4 (N), warp tile 64x64

// ---------------- smem layout (bytes, dynamic) ----------------
#define A_PAD   36           // floats per A row (conflict-free: bank = 4g+tig)
#define A_SZ    (MT * A_PAD * 4)            // 18432
// B: 32 rows x 256 floats, row stride 1024B, 16B-granule XOR swizzle (c ^ (k&3))
#define B_SZ    (KT * DHID * 4)             // 32768
#define STG_SZ  (A_SZ + B_SZ)               // 51200
#define SM_EP   (NSTG * STG_SZ)             // 153600 : 256 x float4 table
#define SM_RED  0                           // reuse stage 0 region post-loop
#define SMEM_TOTAL (SM_EP + DHID * 16)      // 157696

// ---------------- scratch (alloc-free rule: device globals) ----------------
__device__ __align__(16) float g_Arnd[(size_t)BATCH * DIN];           // A rounded to tf32
__device__ __align__(16) float g_W1r[(size_t)NHEADS * DIN * DHID];    // W1 rounded to tf32

#define NA4 ((BATCH * DIN) / 4)
#define NW4 ((NHEADS * DIN * DHID) / 4)

// ---------------- helpers ----------------
__device__ __forceinline__ uint32_t smem_u32(const void* p) {
    uint32_t a;
    asm("{ .reg .u64 t; cvta.to.shared.u64 t, %1; cvt.u32.u64 %0, t; }" : "=r"(a) : "l"(p));
    return a;
}

__device__ __forceinline__ void cp_async16(uint32_t dst, const void* src) {
    asm volatile("cp.async.cg.shared.global [%0], [%1], 16;\n" :: "r"(dst), "l"(src));
}

__device__ __forceinline__ uint32_t lds_u(uint32_t addr) {
    uint32_t v;
    asm volatile("ld.shared.b32 %0, [%1];" : "=r"(v) : "r"(addr));
    return v;
}

__device__ __forceinline__ void mma_tf32(float* d, uint32_t a0, uint32_t a1, uint32_t a2,
                                         uint32_t a3, uint32_t b0, uint32_t b1) {
    asm volatile(
        "mma.sync.aligned.m16n8k8.row.col.f32.tf32.tf32.f32 "
        "{%0,%1,%2,%3}, {%4,%5,%6,%7}, {%8,%9}, {%0,%1,%2,%3};"
        : "+f"(d[0]), "+f"(d[1]), "+f"(d[2]), "+f"(d[3])
        : "r"(a0), "r"(a1), "r"(a2), "r"(a3), "r"(b0), "r"(b1));
}

// ---------------- prep: RN-round fp32 -> tf32 (A and W1 in one launch) ----------------
__global__ void k_prep(const float* __restrict__ A, const float* __restrict__ W) {
    int i = blockIdx.x * blockDim.x + threadIdx.x;
    if (i >= NA4 + NW4) return;
    const float4* src;
    uint4* dst;
    if (i < NA4) {
        src = reinterpret_cast<const float4*>(A) + i;
        dst = reinterpret_cast<uint4*>(g_Arnd) + i;
    } else {
        src = reinterpret_cast<const float4*>(W) + (i - NA4);
        dst = reinterpret_cast<uint4*>(g_W1r) + (i - NA4);
    }
    float4 v = *src;
    uint4 o;
    asm("cvt.rna.tf32.f32 %0, %1;" : "=r"(o.x) : "f"(v.x));
    asm("cvt.rna.tf32.f32 %0, %1;" : "=r"(o.y) : "f"(v.y));
    asm("cvt.rna.tf32.f32 %0, %1;" : "=r"(o.z) : "f"(v.z));
    asm("cvt.rna.tf32.f32 %0, %1;" : "=r"(o.w) : "f"(v.w));
    *dst = o;
}

// ---------------- stage loader ----------------
__device__ __forceinline__ void load_stage(uint32_t stage_base, const float* __restrict__ Ag,
                                           const float* __restrict__ Bg, int kt, int tid) {
    const float* ak = Ag + kt * KT;
#pragma unroll
    for (int i = 0; i < 4; i++) {               // A: 128 rows x 8 granules of 16B
        int gi = tid + i * NTH;
        int r = gi >> 3, c = gi & 7;
        cp_async16(stage_base + r * (A_PAD * 4) + c * 16, ak + (size_t)r * DIN + c * 4);
    }
    const float* bk = Bg + (size_t)kt * KT * DHID;
#pragma unroll
    for (int i = 0; i < 8; i++) {               // B: 32 rows x 64 granules, XOR swizzled
        int gi = tid + i * NTH;
        int r = gi >> 6, c = gi & 63;
        cp_async16(stage_base + A_SZ + r * 1024 + 16 * (c ^ (r & 3)),
                   bk + r * DHID + c * 4);
    }
}

// ---------------- main fused kernel ----------------
__global__ void __launch_bounds__(NTH, 1) mano_gemm(
    const float* __restrict__ b1, const float* __restrict__ W2,
    const float* __restrict__ b2, float* __restrict__ out) {
    extern __shared__ char smem[];
    const uint32_t sb = smem_u32(smem);
    const int tid = threadIdx.x;
    const int wid = tid >> 5, lane = tid & 31;
    const int g = lane >> 2, tig = lane & 3;     // groupID / threadID-in-group
    const int wm = wid & 1, wn = wid >> 1;       // warp tile: rows wm*64, cols wn*64
    const int head = blockIdx.x;                 // head-fastest: L2 reuse of A slab + all W1
    const int m0 = blockIdx.y * MT;

    const float* Ag = g_Arnd + (size_t)m0 * DIN;
    const float* Bg = g_W1r + (size_t)head * DIN * DHID;

    // epilogue table: wb[c] = {b1[c], W2[c][0], W2[c][1], W2[c][2]}
    if (tid < DHID) {
        const float* b1h = b1 + head * DHID;
        const float* w2h = W2 + (size_t)head * DHID * DOUT;
        float4 v;
        v.x = b1h[tid];
        v.y = w2h[tid * 3 + 0];
        v.z = w2h[tid * 3 + 1];
        v.w = w2h[tid * 3 + 2];
        *reinterpret_cast<float4*>(smem + SM_EP + tid * 16) = v;
    }

    // prologue: stages 0,1 in flight
    load_stage(sb + 0 * STG_SZ, Ag, Bg, 0, tid);
    asm volatile("cp.async.commit_group;\n");
    load_stage(sb + 1 * STG_SZ, Ag, Bg, 1, tid);
    asm volatile("cp.async.commit_group;\n");

    // precomputed swizzled B column byte-offsets (within a row) per j
    uint32_t nsw[8];
#pragma unroll
    for (int j = 0; j < 8; j++) {
        int n = wn * 64 + j * 8 + g;
        nsw[j] = 16u * ((uint32_t)(n >> 2) ^ (uint32_t)tig) + 4u * (n & 3);
    }
    // A row byte offsets (within a stage) for the 8 fragment rows
    uint32_t arow[8];
#pragma unroll
    for (int t = 0; t < 4; t++) {
        int r0 = wm * 64 + t * 16 + g;
        arow[t * 2 + 0] = (uint32_t)(r0 * A_PAD + tig) * 4u;
        arow[t * 2 + 1] = (uint32_t)((r0 + 8) * A_PAD + tig) * 4u;
    }

    float acc[4][8][4];
#pragma unroll
    for (int t = 0; t < 4; t++)
#pragma unroll
        for (int j = 0; j < 8; j++)
#pragma unroll
            for (int e = 0; e < 4; e++) acc[t][j][e] = 0.f;

    // fragment double buffers
    uint32_t aF[2][16], bF[2][16];

    for (int kt = 0; kt < NK; kt++) {
        const int buf = kt % NSTG;
        asm volatile("cp.async.wait_group 1;\n");   // stage kt landed
        __syncthreads();                            // all warps done with prior buffer

        const uint32_t a_base = sb + buf * STG_SZ;
        const uint32_t b_base = a_base + A_SZ;

        // load fragments for k8=0 into buffer 0
#pragma unroll
        for (int t = 0; t < 4; t++) {
            aF[0][t * 4 + 0] = lds_u(a_base + arow[t * 2 + 0]);
            aF[0][t * 4 + 1] = lds_u(a_base + arow[t * 2 + 1]);
            aF[0][t * 4 + 2] = lds_u(a_base + arow[t * 2 + 0] + 16u);
            aF[0][t * 4 + 3] = lds_u(a_base + arow[t * 2 + 1] + 16u);
        }
        {
            const uint32_t brow0 = b_base + (uint32_t)tig * 1024u;
#pragma unroll
            for (int j = 0; j < 8; j++) {
                bF[0][j * 2 + 0] = lds_u(brow0 + nsw[j]);
                bF[0][j * 2 + 1] = lds_u(brow0 + 4096u + nsw[j]);
            }
        }

        // prefetch next stage while fragments are in flight
        if (kt + 2 < NK)
            load_stage(sb + ((kt + 2) % NSTG) * STG_SZ, Ag, Bg, kt + 2, tid);
        asm volatile("cp.async.commit_group;\n");

#pragma unroll
        for (int k8 = 0; k8 < 4; k8++) {
            const int cur = k8 & 1, nxt = cur ^ 1;
            // issue next step's 32 LDS before this step's HMMAs
            if (k8 < 3) {
                const uint32_t koff = (uint32_t)((k8 + 1) * 8) * 4u;
#pragma unroll
                for (int t = 0; t < 4; t++) {
                    aF[nxt][t * 4 + 0] = lds_u(a_base + arow[t * 2 + 0] + koff);
                    aF[nxt][t * 4 + 1] = lds_u(a_base + arow[t * 2 + 1] + koff);
                    aF[nxt][t * 4 + 2] = lds_u(a_base + arow[t * 2 + 0] + koff + 16u);
                    aF[nxt][t * 4 + 3] = lds_u(a_base + arow[t * 2 + 1] + koff + 16u);
                }
                const uint32_t brow0 = b_base + (uint32_t)((k8 + 1) * 8 + tig) * 1024u;
#pragma unroll
                for (int j = 0; j < 8; j++) {
                    bF[nxt][j * 2 + 0] = lds_u(brow0 + nsw[j]);
                    bF[nxt][j * 2 + 1] = lds_u(brow0 + 4096u + nsw[j]);
                }
            }
            // 32 HMMAs on current buffer
#pragma unroll
            for (int j = 0; j < 8; j++) {
#pragma unroll
                for (int t = 0; t < 4; t++)
                    mma_tf32(acc[t][j], aF[cur][t * 4 + 0], aF[cur][t * 4 + 1],
                             aF[cur][t * 4 + 2], aF[cur][t * 4 + 3],
                             bF[cur][j * 2 + 0], bF[cur][j * 2 + 1]);
            }
        }
    }

    __syncthreads();    // done reading stage smem; safe to reuse region 0 for reduction

    // ---- fused epilogue: h = relu(acc + b1); partial[p] += h * W2[:,p] ----
    float s[4][2][3];
#pragma unroll
    for (int t = 0; t < 4; t++)
#pragma unroll
        for (int h = 0; h < 2; h++)
            s[t][h][0] = s[t][h][1] = s[t][h][2] = 0.f;

#pragma unroll
    for (int j = 0; j < 8; j++) {
#pragma unroll
        for (int e = 0; e < 2; e++) {
            const int c = wn * 64 + j * 8 + tig * 2 + e;
            const float4 wv = *reinterpret_cast<const float4*>(smem + SM_EP + c * 16);
#pragma unroll
            for (int t = 0; t < 4; t++) {
#pragma unroll
                for (int h = 0; h < 2; h++) {
                    float hv = fmaxf(acc[t][j][h * 2 + e] + wv.x, 0.f);
                    s[t][h][0] = fmaf(hv, wv.y, s[t][h][0]);
                    s[t][h][1] = fmaf(hv, wv.z, s[t][h][1]);
                    s[t][h][2] = fmaf(hv, wv.w, s[t][h][2]);
                }
            }
        }
    }

    // reduce over tig (lanes sharing a row): lane bits 0,1
#pragma unroll
    for (int t = 0; t < 4; t++)
#pragma unroll
        for (int h = 0; h < 2; h++)
#pragma unroll
            for (int p = 0; p < 3; p++) {
                float v = s[t][h][p];
                v += __shfl_xor_sync(0xffffffffu, v, 1);
                v += __shfl_xor_sync(0xffffffffu, v, 2);
                s[t][h][p] = v;
            }

    // cross-warp (wn) reduction through smem: red[wn][row][p]
    float* red = reinterpret_cast<float*>(smem + SM_RED);
    if (tig == 0) {
#pragma unroll
        for (int t = 0; t < 4; t++)
#pragma unroll
            for (int h = 0; h < 2; h++) {
                int row = wm * 64 + t * 16 + h * 8 + g;
#pragma unroll
                for (int p = 0; p < 3; p++)
                    red[(wn * MT + row) * 3 + p] = s[t][h][p];
            }
    }
    __syncthreads();

    for (int i = tid; i < MT * 3; i += NTH) {
        int r = i / 3, p = i % 3;
        float v = red[(0 * MT + r) * 3 + p] + red[(1 * MT + r) * 3 + p]
                + red[(2 * MT + r) * 3 + p] + red[(3 * MT + r) * 3 + p]
                + __ldg(b2 + head * DOUT + p);
        out[(size_t)(m0 + r) * (NHEADS * DOUT) + head * DOUT + p] = v;
    }
}

// ---------------- launch ----------------
extern "C" void kernel_launch(void* const* d_in, const int* in_sizes, int n_in,
                              void* d_out, int out_size) {
    const float* total_feat = (const float*)d_in[0];
    const float* W1 = (const float*)d_in[1];
    const float* b1 = (const float*)d_in[2];
    const float* W2 = (const float*)d_in[3];
    const float* b2 = (const float*)d_in[4];
    float* out = (float*)d_out;

    int total = NA4 + NW4;
    k_prep<<<(total + 255) / 256, 256>>>(total_feat, W1);

    cudaFuncSetAttribute(mano_gemm, cudaFuncAttributeMaxDynamicSharedMemorySize, SMEM_TOTAL);
    mano_gemm<<<dim3(NHEADS, BATCH / MT), NTH, SMEM_TOTAL>>>(b1, W2, b2, out);
}

// round 14
// speedup vs baseline: 2.1377x; 1.8560x over previous
#include <cuda_runtime.h>
#include <cuda_fp16.h>
#include <cstdint>

// ---------------- problem constants ----------------
#define BATCH   16384
#define DIN     1408
#define DHID    256
#define DOUT    3
#define NHEADS  32
#define KPAIRS  (DIN / 2)    // 704

// ---------------- tiling ----------------
#define MT      128          // CTA rows
#define KT      64           // K per stage (fp16)
#define NK      (DIN / KT)   // 22
#define NSTG    3
#define NTH     256          // 8 warps: 2 (M) x 4 (N), warp tile 64x64

// ---------------- smem layout (bytes, dynamic) ----------------
// A: 128 rows x 32 kpairs (128B data) + 16B pad -> stride 144B
//    fragment loads: bank = 4g + tig  (bijective)  | stores conflict-free
#define A_STRIDE 144
#define A_SZ    (MT * A_STRIDE)             // 18432
// B: 32 kpair-rows x 256 n (1024B data) + 32B pad -> stride 1056B (== 8 mod 32 banks)
//    fragment loads: bank = 8*tig + g  (bijective) | stores conflict-free
#define B_STRIDE 1056
#define B_SZ    ((KT / 2) * B_STRIDE)       // 33792
#define STG_SZ  (A_SZ + B_SZ)               // 52224
#define SM_EP   (NSTG * STG_SZ)             // 156672 : 256 x float4 table
#define SM_RED  0                           // reuse stage 0 region post-loop
#define SMEM_TOTAL (SM_EP + DHID * 16)      // 160768

// ---------------- scratch (alloc-free rule: device globals) ----------------
__device__ __align__(16) __half g_Ah[(size_t)BATCH * DIN];            // A as fp16 [m][k]
__device__ __align__(16) uint32_t g_W1p[(size_t)NHEADS * KPAIRS * DHID]; // [h][kpair][n] half2

// ---------------- helpers ----------------
__device__ __forceinline__ uint32_t smem_u32(const void* p) {
    uint32_t a;
    asm("{ .reg .u64 t; cvta.to.shared.u64 t, %1; cvt.u32.u64 %0, t; }" : "=r"(a) : "l"(p));
    return a;
}

__device__ __forceinline__ void cp_async16(uint32_t dst, const void* src) {
    asm volatile("cp.async.cg.shared.global [%0], [%1], 16;\n" :: "r"(dst), "l"(src));
}

__device__ __forceinline__ uint32_t lds_u(uint32_t addr) {
    uint32_t v;
    asm volatile("ld.shared.b32 %0, [%1];" : "=r"(v) : "r"(addr));
    return v;
}

__device__ __forceinline__ void mma_f16(float* d, uint32_t a0, uint32_t a1, uint32_t a2,
                                        uint32_t a3, uint32_t b0, uint32_t b1) {
    asm volatile(
        "mma.sync.aligned.m16n8k16.row.col.f32.f16.f16.f32 "
        "{%0,%1,%2,%3}, {%4,%5,%6,%7}, {%8,%9}, {%0,%1,%2,%3};"
        : "+f"(d[0]), "+f"(d[1]), "+f"(d[2]), "+f"(d[3])
        : "r"(a0), "r"(a1), "r"(a2), "r"(a3), "r"(b0), "r"(b1));
}

__device__ __forceinline__ uint32_t pack_h2(float lo, float hi) {
    __half2 h = __halves2half2(__float2half_rn(lo), __float2half_rn(hi));
    return *reinterpret_cast<uint32_t*>(&h);
}

// ---------------- prep 1: A fp32 -> fp16 (natural [m][k] order) ----------------
__global__ void k_prep_a(const float* __restrict__ A) {
    int i = blockIdx.x * blockDim.x + threadIdx.x;     // 8 floats per thread
    if (i >= (BATCH * DIN) / 8) return;
    const float4* src = reinterpret_cast<const float4*>(A) + 2 * i;
    float4 v0 = src[0], v1 = src[1];
    uint4 o;
    o.x = pack_h2(v0.x, v0.y);
    o.y = pack_h2(v0.z, v0.w);
    o.z = pack_h2(v1.x, v1.y);
    o.w = pack_h2(v1.z, v1.w);
    reinterpret_cast<uint4*>(g_Ah)[i] = o;
}

// ---------------- prep 2: W1 [h][f][o] -> [h][kpair][n] half2 ----------------
__global__ void k_prep_w(const float* __restrict__ W1) {
    int i = blockIdx.x * blockDim.x + threadIdx.x;     // 4 n-values per thread
    int total = NHEADS * KPAIRS * (DHID / 4);
    if (i >= total) return;
    int n4 = i % (DHID / 4);
    int kp = (i / (DHID / 4)) % KPAIRS;
    int h  = i / ((DHID / 4) * KPAIRS);
    const float* r0 = W1 + ((size_t)h * DIN + 2 * kp) * DHID + n4 * 4;
    const float* r1 = r0 + DHID;
    float4 a = *reinterpret_cast<const float4*>(r0);
    float4 b = *reinterpret_cast<const float4*>(r1);
    uint4 o;
    o.x = pack_h2(a.x, b.x);
    o.y = pack_h2(a.y, b.y);
    o.z = pack_h2(a.z, b.z);
    o.w = pack_h2(a.w, b.w);
    *reinterpret_cast<uint4*>(&g_W1p[((size_t)h * KPAIRS + kp) * DHID + n4 * 4]) = o;
}

// ---------------- stage loader ----------------
__device__ __forceinline__ void load_stage(uint32_t stage_base, const __half* __restrict__ Ag,
                                           const uint32_t* __restrict__ Bg, int kt, int tid) {
    const __half* ak = Ag + kt * KT;
#pragma unroll
    for (int i = 0; i < 4; i++) {               // A: 128 rows x 8 granules of 16B
        int gi = tid + i * NTH;
        int r = gi >> 3, c = gi & 7;
        cp_async16(stage_base + r * A_STRIDE + c * 16, ak + (size_t)r * DIN + c * 8);
    }
    const uint32_t* bk = Bg + (size_t)kt * (KT / 2) * DHID;
#pragma unroll
    for (int i = 0; i < 8; i++) {               // B: 32 kpair-rows x 64 granules of 16B
        int gi = tid + i * NTH;
        int r = gi >> 6, c = gi & 63;
        cp_async16(stage_base + A_SZ + r * B_STRIDE + c * 16, bk + r * DHID + c * 4);
    }
}

// ---------------- main fused kernel ----------------
__global__ void __launch_bounds__(NTH, 1) mano_gemm(
    const float* __restrict__ b1, const float* __restrict__ W2,
    const float* __restrict__ b2, float* __restrict__ out) {
    extern __shared__ char smem[];
    const uint32_t sb = smem_u32(smem);
    const int tid = threadIdx.x;
    const int wid = tid >> 5, lane = tid & 31;
    const int g = lane >> 2, tig = lane & 3;     // groupID / threadID-in-group
    const int wm = wid & 1, wn = wid >> 1;       // warp tile: rows wm*64, cols wn*64
    const int head = blockIdx.x;                 // head-fastest: L2 reuse of A slab + all W1
    const int m0 = blockIdx.y * MT;

    const __half* Ag = g_Ah + (size_t)m0 * DIN;
    const uint32_t* Bg = g_W1p + (size_t)head * KPAIRS * DHID;

    // epilogue table: wb[c] = {b1[c], W2[c][0], W2[c][1], W2[c][2]}
    if (tid < DHID) {
        const float* b1h = b1 + head * DHID;
        const float* w2h = W2 + (size_t)head * DHID * DOUT;
        float4 v;
        v.x = b1h[tid];
        v.y = w2h[tid * 3 + 0];
        v.z = w2h[tid * 3 + 1];
        v.w = w2h[tid * 3 + 2];
        *reinterpret_cast<float4*>(smem + SM_EP + tid * 16) = v;
    }

    // prologue: stages 0,1 in flight
    load_stage(sb + 0 * STG_SZ, Ag, Bg, 0, tid);
    asm volatile("cp.async.commit_group;\n");
    load_stage(sb + 1 * STG_SZ, Ag, Bg, 1, tid);
    asm volatile("cp.async.commit_group;\n");

    // per-thread constant offsets
    uint32_t nb[8];                               // B: n-column byte offset
#pragma unroll
    for (int j = 0; j < 8; j++)
        nb[j] = (uint32_t)(wn * 64 + j * 8 + g) * 4u;
    uint32_t arow[4][2];                          // A: row byte offsets (+ tig kpair)
#pragma unroll
    for (int t = 0; t < 4; t++) {
        int r0 = wm * 64 + t * 16 + g;
        arow[t][0] = (uint32_t)(r0 * A_STRIDE) + (uint32_t)tig * 4u;
        arow[t][1] = (uint32_t)((r0 + 8) * A_STRIDE) + (uint32_t)tig * 4u;
    }

    float acc[4][8][4];
#pragma unroll
    for (int t = 0; t < 4; t++)
#pragma unroll
        for (int j = 0; j < 8; j++)
#pragma unroll
            for (int e = 0; e < 4; e++) acc[t][j][e] = 0.f;

    for (int kt = 0; kt < NK; kt++) {
        const int buf = kt % NSTG;
        asm volatile("cp.async.wait_group 1;\n");   // stage kt landed
        __syncthreads();                            // all warps done with prior buffer

        if (kt + 2 < NK)
            load_stage(sb + ((kt + 2) % NSTG) * STG_SZ, Ag, Bg, kt + 2, tid);
        asm volatile("cp.async.commit_group;\n");

        const uint32_t a_base = sb + buf * STG_SZ;
        const uint32_t b_base = a_base + A_SZ;
#pragma unroll
        for (int s = 0; s < 4; s++) {               // 4 x m16n8k16 steps (kpairs 8s..8s+7)
            const uint32_t akoff = (uint32_t)(s * 8) * 4u;       // +8 kpairs
            uint32_t a0[4], a1[4], a2[4], a3[4];
#pragma unroll
            for (int t = 0; t < 4; t++) {
                a0[t] = lds_u(a_base + arow[t][0] + akoff);
                a1[t] = lds_u(a_base + arow[t][1] + akoff);
                a2[t] = lds_u(a_base + arow[t][0] + akoff + 16u);
                a3[t] = lds_u(a_base + arow[t][1] + akoff + 16u);
            }
            const uint32_t brow0 = b_base + (uint32_t)(s * 8 + tig) * B_STRIDE;
#pragma unroll
            for (int j = 0; j < 8; j++) {
                uint32_t b0 = lds_u(brow0 + nb[j]);
                uint32_t b1r = lds_u(brow0 + 4u * B_STRIDE + nb[j]);
#pragma unroll
                for (int t = 0; t < 4; t++)
                    mma_f16(acc[t][j], a0[t], a1[t], a2[t], a3[t], b0, b1r);
            }
        }
    }

    __syncthreads();    // done reading stage smem; safe to reuse region 0 for reduction

    // ---- fused epilogue: h = relu(acc + b1); partial[p] += h * W2[:,p] ----
    float s[4][2][3];
#pragma unroll
    for (int t = 0; t < 4; t++)
#pragma unroll
        for (int h = 0; h < 2; h++)
            s[t][h][0] = s[t][h][1] = s[t][h][2] = 0.f;

#pragma unroll
    for (int j = 0; j < 8; j++) {
#pragma unroll
        for (int e = 0; e < 2; e++) {
            const int c = wn * 64 + j * 8 + tig * 2 + e;
            const float4 wv = *reinterpret_cast<const float4*>(smem + SM_EP + c * 16);
#pragma unroll
            for (int t = 0; t < 4; t++) {
#pragma unroll
                for (int h = 0; h < 2; h++) {
                    float hv = fmaxf(acc[t][j][h * 2 + e] + wv.x, 0.f);
                    s[t][h][0] = fmaf(hv, wv.y, s[t][h][0]);
                    s[t][h][1] = fmaf(hv, wv.z, s[t][h][1]);
                    s[t][h][2] = fmaf(hv, wv.w, s[t][h][2]);
                }
            }
        }
    }

    // reduce over tig (lanes sharing a row): lane bits 0,1
#pragma unroll
    for (int t = 0; t < 4; t++)
#pragma unroll
        for (int h = 0; h < 2; h++)
#pragma unroll
            for (int p = 0; p < 3; p++) {
                float v = s[t][h][p];
                v += __shfl_xor_sync(0xffffffffu, v, 1);
                v += __shfl_xor_sync(0xffffffffu, v, 2);
                s[t][h][p] = v;
            }

    // cross-warp (wn) reduction through smem: red[wn][row][p]
    float* red = reinterpret_cast<float*>(smem + SM_RED);
    if (tig == 0) {
#pragma unroll
        for (int t = 0; t < 4; t++)
#pragma unroll
            for (int h = 0; h < 2; h++) {
                int row = wm * 64 + t * 16 + h * 8 + g;
#pragma unroll
                for (int p = 0; p < 3; p++)
                    red[(wn * MT + row) * 3 + p] = s[t][h][p];
            }
    }
    __syncthreads();

    for (int i = tid; i < MT * 3; i += NTH) {
        int r = i / 3, p = i % 3;
        float v = red[(0 * MT + r) * 3 + p] + red[(1 * MT + r) * 3 + p]
                + red[(2 * MT + r) * 3 + p] + red[(3 * MT + r) * 3 + p]
                + __ldg(b2 + head * DOUT + p);
        out[(size_t)(m0 + r) * (NHEADS * DOUT) + head * DOUT + p] = v;
    }
}

// ---------------- launch ----------------
extern "C" void kernel_launch(void* const* d_in, const int* in_sizes, int n_in,
                              void* d_out, int out_size) {
    const float* total_feat = (const float*)d_in[0];
    const float* W1 = (const float*)d_in[1];
    const float* b1 = (const float*)d_in[2];
    const float* W2 = (const float*)d_in[3];
    const float* b2 = (const float*)d_in[4];
    float* out = (float*)d_out;

    int nA = (BATCH * DIN) / 8;
    k_prep_a<<<(nA + 255) / 256, 256>>>(total_feat);
    int nW = NHEADS * KPAIRS * (DHID / 4);
    k_prep_w<<<(nW + 255) / 256, 256>>>(W1);

    cudaFuncSetAttribute(mano_gemm, cudaFuncAttributeMaxDynamicSharedMemorySize, SMEM_TOTAL);
    mano_gemm<<<dim3(NHEADS, BATCH / MT), NTH, SMEM_TOTAL>>>(b1, W2, b2, out);
}